// round 2
// baseline (speedup 1.0000x reference)
#include <cuda_runtime.h>

// SPDUnVectorize: out[b,i,j] = x[b, tri(min(i,j), max(i,j))]
// tri(i,j) for i<=j (row-major upper triangle): i*N - i*(i-1)/2 + (j-i)
//
// Strategy: 1 CTA per batch row. Stage the 32896-float triangle vector in
// dynamic shared memory (131584 B), then emit the full 256x256 matrix with
// coalesced float4 stores. DRAM traffic = 1x read + 1x write (minimum).

#define NMAT 256
#define DTRI (NMAT * (NMAT + 1) / 2)   // 32896
#define SMEM_BYTES (DTRI * 4)          // 131584
#define THREADS 1024

__global__ void __launch_bounds__(THREADS, 1)
spd_unvec_kernel(const float* __restrict__ x, float* __restrict__ out) {
    extern __shared__ float xs[];

    const int b = blockIdx.x;
    const int t = threadIdx.x;

    // ---- Stage input row into shared memory (coalesced float4 loads) ----
    const float4* __restrict__ xin = reinterpret_cast<const float4*>(x + (size_t)b * DTRI);
    float4* xs4 = reinterpret_cast<float4*>(xs);
    // DTRI/4 = 8224 float4 elements; 1024 threads -> 8 full iters + 32 tail
    #pragma unroll
    for (int i = t; i < DTRI / 4; i += THREADS) {
        xs4[i] = xin[i];
    }
    __syncthreads();

    // ---- Emit full symmetric matrix (coalesced float4 stores) ----
    float* __restrict__ o = out + (size_t)b * (NMAT * NMAT);

    const int j0 = (t & 63) << 2;     // column group: 0,4,...,252
    const int i0 = t >> 6;            // row start: 0..15

    #pragma unroll
    for (int i = i0; i < NMAT; i += 16) {
        float4 v;
        #pragma unroll
        for (int c = 0; c < 4; c++) {
            const int j = j0 + c;
            const int lo = (i < j) ? i : j;
            const int hi = (i < j) ? j : i;
            const int idx = lo * NMAT - (lo * (lo - 1)) / 2 + (hi - lo);
            (&v.x)[c] = xs[idx];
        }
        *reinterpret_cast<float4*>(o + i * NMAT + j0) = v;
    }
}

extern "C" void kernel_launch(void* const* d_in, const int* in_sizes, int n_in,
                              void* d_out, int out_size) {
    const float* x = (const float*)d_in[0];
    float* out = (float*)d_out;

    const int B = out_size / (NMAT * NMAT);   // 4096

    cudaFuncSetAttribute(spd_unvec_kernel,
                         cudaFuncAttributeMaxDynamicSharedMemorySize, SMEM_BYTES);

    spd_unvec_kernel<<<B, THREADS, SMEM_BYTES>>>(x, out);
}

// round 3
// speedup vs baseline: 1.1276x; 1.1276x over previous
#include <cuda_runtime.h>

// SPDUnVectorize: out[b,i,j] = x[b, tri(min(i,j), max(i,j))]
// tri(i,j), i<=j: i*N - i*(i-1)/2 + (j-i)
//
// Tiled symmetric expansion: one CTA per 64x64 tile of the upper-triangular
// block grid (10 tiles per batch row of the 4x4 block grid). Off-diagonal
// CTAs read the packed tile once, write it straight out AND write its
// transpose via smem. Diagonal CTAs mirror in smem. Small smem footprint
// (16.6KB) -> high occupancy, fully interleaved read/write DRAM traffic.

#define NMAT 256
#define DTRI (NMAT * (NMAT + 1) / 2)   // 32896
#define TB 64
#define NTB (NMAT / TB)                 // 4
#define NTILES (NTB * (NTB + 1) / 2)    // 10
#define THREADS 256

__constant__ int c_tbi[NTILES] = {0,0,0,0,1,1,1,2,2,3};
__constant__ int c_tbj[NTILES] = {0,1,2,3,1,2,3,2,3,3};

__global__ void __launch_bounds__(THREADS)
spd_unvec_tiled(const float* __restrict__ x, float* __restrict__ out) {
    __shared__ float s[TB][TB + 1];

    const int t    = threadIdx.x;
    const int b    = blockIdx.y;
    const int tile = blockIdx.x;
    const int bi = c_tbi[tile];
    const int bj = c_tbj[tile];

    const float* __restrict__ xr = x + (size_t)b * DTRI;
    float* __restrict__ o = out + (size_t)b * (NMAT * NMAT);

    const int r0 = t >> 4;          // 0..15 (row within pass)
    const int c0 = (t & 15) << 2;   // 0,4,...,60 (float col within tile)

    if (bi != bj) {
        // ---- load packed tile + write upper out tile directly ----
        #pragma unroll
        for (int k = 0; k < 4; k++) {
            const int r = r0 + k * 16;
            const int i = bi * TB + r;
            // tri(i, bj*TB + c) = base + c
            const int base = i * NMAT - (i * (i - 1)) / 2 - i + bj * TB;
            float4 v;
            v.x = xr[base + c0 + 0];
            v.y = xr[base + c0 + 1];
            v.z = xr[base + c0 + 2];
            v.w = xr[base + c0 + 3];
            *reinterpret_cast<float4*>(o + i * NMAT + bj * TB + c0) = v;
            s[r][c0 + 0] = v.x;
            s[r][c0 + 1] = v.y;
            s[r][c0 + 2] = v.z;
            s[r][c0 + 3] = v.w;
        }
        __syncthreads();

        // ---- write transposed tile to out[bj, bi] ----
        #pragma unroll
        for (int k = 0; k < 4; k++) {
            const int rr = r0 + k * 16;       // row of transposed tile
            const int j  = bj * TB + rr;
            float4 v;
            v.x = s[c0 + 0][rr];
            v.y = s[c0 + 1][rr];
            v.z = s[c0 + 2][rr];
            v.w = s[c0 + 3][rr];
            *reinterpret_cast<float4*>(o + j * NMAT + bi * TB + c0) = v;
        }
    } else {
        // ---- diagonal tile: load upper part, mirror lower ----
        #pragma unroll
        for (int k = 0; k < 4; k++) {
            const int r = r0 + k * 16;
            const int i = bi * TB + r;
            const int base = i * NMAT - (i * (i - 1)) / 2 - i + bi * TB;
            #pragma unroll
            for (int q = 0; q < 4; q++) {
                const int c = c0 + q;
                s[r][c] = (c >= r) ? xr[base + c] : 0.0f;
            }
        }
        __syncthreads();

        #pragma unroll
        for (int k = 0; k < 4; k++) {
            const int r = r0 + k * 16;
            const int i = bi * TB + r;
            float4 v;
            #pragma unroll
            for (int q = 0; q < 4; q++) {
                const int c = c0 + q;
                (&v.x)[q] = (c >= r) ? s[r][c] : s[c][r];
            }
            *reinterpret_cast<float4*>(o + i * NMAT + bi * TB + c0) = v;
        }
    }
}

extern "C" void kernel_launch(void* const* d_in, const int* in_sizes, int n_in,
                              void* d_out, int out_size) {
    const float* x = (const float*)d_in[0];
    float* out = (float*)d_out;

    const int B = out_size / (NMAT * NMAT);   // 4096

    dim3 grid(NTILES, B);
    spd_unvec_tiled<<<grid, THREADS>>>(x, out);
}